// round 14
// baseline (speedup 1.0000x reference)
#include <cuda_runtime.h>
#include <cuda_fp16.h>
#include <math.h>

#define NN 150000
#define EE 4800000
#define H 16
#define CAP 128              // bucket capacity per node (max degree ~75 for Poisson(32))

// ---------------- scratch (device globals) ----------------------------------
__device__ int   g_is64;
__device__ int   g_cnt[NN];                         // in-degree (excl. self loop)
__device__ __align__(16) int g_bkt[NN * CAP];       // per-dst src buckets (76.8 MB)
__device__ float g_dinv[NN];
__device__ __align__(128) __half2 g_hs1[NN * 8];    // 16 halves per node (32B rows)
__device__ __align__(128) __half2 g_hs2[NN * 8];
__device__ float g_hs3[NN];

__device__ __forceinline__ unsigned h2u(__half2 h) {
    return *reinterpret_cast<unsigned*>(&h);
}

// ---------------- init: zero counts + detect dtype ------------------------------

__global__ void k_init(const void* __restrict__ ei, int ne, int n) {
    int i = blockIdx.x * blockDim.x + threadIdx.x;
    if (i < n) g_cnt[i] = 0;
    if (blockIdx.x == 0 && threadIdx.x < 32) {
        const long long* p = (const long long*)ei;
        int lane = threadIdx.x;
        int bad = 0;
        int lim = ne < 1024 ? ne : 1024;
        for (int e = lane; e < lim; e += 32) {
            long long v = p[e];
            if (v < 0 || v >= NN) bad = 1;
        }
        unsigned m = __ballot_sync(0xffffffffu, bad);
        if (lane == 0) g_is64 = (m == 0) ? 1 : 0;
    }
}

// ---------------- single-pass bucket build (2 edges/thread) -----------------------

__global__ void k_build(const void* __restrict__ ei, int ne) {
    int t = blockIdx.x * blockDim.x + threadIdx.x;
    int e0 = t * 2;
    if (e0 >= ne) return;
    bool two = (e0 + 1 < ne);
    int s0, d0, s1 = 0, d1 = 0;
    if (g_is64) {
        const long long* p = (const long long*)ei;
        if (two) {
            longlong2 sp = *(const longlong2*)&p[e0];
            longlong2 dp = *(const longlong2*)&p[ne + e0];
            s0 = (int)sp.x; s1 = (int)sp.y;
            d0 = (int)dp.x; d1 = (int)dp.y;
        } else {
            s0 = (int)p[e0];
            d0 = (int)p[ne + e0];
        }
    } else {
        const int* p = (const int*)ei;
        if (two) {
            int2 sp = *(const int2*)&p[e0];
            int2 dp = *(const int2*)&p[ne + e0];
            s0 = sp.x; s1 = sp.y; d0 = dp.x; d1 = dp.y;
        } else {
            s0 = p[e0];
            d0 = p[ne + e0];
        }
    }
    s0 = min(max(s0, 0), NN - 1); d0 = min(max(d0, 0), NN - 1);
    int p0 = atomicAdd(&g_cnt[d0], 1);
    if (p0 < CAP) g_bkt[d0 * CAP + p0] = s0;
    if (two) {
        s1 = min(max(s1, 0), NN - 1); d1 = min(max(d1, 0), NN - 1);
        int p1 = atomicAdd(&g_cnt[d1], 1);
        if (p1 < CAP) g_bkt[d1 * CAP + p1] = s1;
    }
}

// ---------------- layer-1 node transform ------------------------------------------

__global__ void k_node1(const float* __restrict__ x,
                        const float* __restrict__ Win, int n) {
    __shared__ float w[48];
    if (threadIdx.x < 48) w[threadIdx.x] = Win[threadIdx.x];
    __syncthreads();
    int i = blockIdx.x * blockDim.x + threadIdx.x;
    if (i >= n) return;
    float di = rsqrtf((float)(g_cnt[i] + 1));
    g_dinv[i] = di;
    float x0 = x[i * 3 + 0], x1 = x[i * 3 + 1], x2 = x[i * 3 + 2];
    float v[16];
#pragma unroll
    for (int j = 0; j < 16; j++)
        v[j] = di * (x0 * w[j] + x1 * w[16 + j] + x2 * w[32 + j]);
    uint4 pk0, pk1;
    pk0.x = h2u(__floats2half2_rn(v[0],  v[1]));
    pk0.y = h2u(__floats2half2_rn(v[2],  v[3]));
    pk0.z = h2u(__floats2half2_rn(v[4],  v[5]));
    pk0.w = h2u(__floats2half2_rn(v[6],  v[7]));
    pk1.x = h2u(__floats2half2_rn(v[8],  v[9]));
    pk1.y = h2u(__floats2half2_rn(v[10], v[11]));
    pk1.z = h2u(__floats2half2_rn(v[12], v[13]));
    pk1.w = h2u(__floats2half2_rn(v[14], v[15]));
    ((uint4*)g_hs1)[i * 2 + 0] = pk0;
    ((uint4*)g_hs1)[i * 2 + 1] = pk1;
}

// ---------------- fused gather kernels (half2 rows, quad-per-node) ------------------

__device__ __forceinline__ void acc_row(float4& acc, uint2 raw) {
    float2 f0 = __half22float2(*reinterpret_cast<const __half2*>(&raw.x));
    float2 f1 = __half22float2(*reinterpret_cast<const __half2*>(&raw.y));
    acc.x += f0.x; acc.y += f0.y; acc.z += f1.x; acc.w += f1.y;
}

// Bucket gather: 16-edge unroll (4 int4 idx loads, 16 independent row loads),
// then 8/4/1 tails.
__device__ __forceinline__ float4 gather_rows(const uint2* __restrict__ hs,
                                              int i, int q) {
    float4 acc = make_float4(0.f, 0.f, 0.f, 0.f);
    acc_row(acc, __ldg(&hs[i * 4 + q]));           // self loop
    const int4* __restrict__ row4 = (const int4*)&g_bkt[i * CAP];
    const int*  __restrict__ row  = &g_bkt[i * CAP];
    int end = min(g_cnt[i], CAP);
    int e = 0;
    for (; e + 15 < end; e += 16) {
        int4 sa = __ldg(&row4[(e >> 2) + 0]);
        int4 sb = __ldg(&row4[(e >> 2) + 1]);
        int4 sc = __ldg(&row4[(e >> 2) + 2]);
        int4 sd = __ldg(&row4[(e >> 2) + 3]);
        uint2 r0 = __ldg(&hs[sa.x * 4 + q]);
        uint2 r1 = __ldg(&hs[sa.y * 4 + q]);
        uint2 r2 = __ldg(&hs[sa.z * 4 + q]);
        uint2 r3 = __ldg(&hs[sa.w * 4 + q]);
        uint2 r4 = __ldg(&hs[sb.x * 4 + q]);
        uint2 r5 = __ldg(&hs[sb.y * 4 + q]);
        uint2 r6 = __ldg(&hs[sb.z * 4 + q]);
        uint2 r7 = __ldg(&hs[sb.w * 4 + q]);
        uint2 r8 = __ldg(&hs[sc.x * 4 + q]);
        uint2 r9 = __ldg(&hs[sc.y * 4 + q]);
        uint2 rA = __ldg(&hs[sc.z * 4 + q]);
        uint2 rB = __ldg(&hs[sc.w * 4 + q]);
        uint2 rC = __ldg(&hs[sd.x * 4 + q]);
        uint2 rD = __ldg(&hs[sd.y * 4 + q]);
        uint2 rE = __ldg(&hs[sd.z * 4 + q]);
        uint2 rF = __ldg(&hs[sd.w * 4 + q]);
        acc_row(acc, r0); acc_row(acc, r1); acc_row(acc, r2); acc_row(acc, r3);
        acc_row(acc, r4); acc_row(acc, r5); acc_row(acc, r6); acc_row(acc, r7);
        acc_row(acc, r8); acc_row(acc, r9); acc_row(acc, rA); acc_row(acc, rB);
        acc_row(acc, rC); acc_row(acc, rD); acc_row(acc, rE); acc_row(acc, rF);
    }
    if (e + 7 < end) {
        int4 sa = __ldg(&row4[(e >> 2) + 0]);
        int4 sb = __ldg(&row4[(e >> 2) + 1]);
        uint2 r0 = __ldg(&hs[sa.x * 4 + q]);
        uint2 r1 = __ldg(&hs[sa.y * 4 + q]);
        uint2 r2 = __ldg(&hs[sa.z * 4 + q]);
        uint2 r3 = __ldg(&hs[sa.w * 4 + q]);
        uint2 r4 = __ldg(&hs[sb.x * 4 + q]);
        uint2 r5 = __ldg(&hs[sb.y * 4 + q]);
        uint2 r6 = __ldg(&hs[sb.z * 4 + q]);
        uint2 r7 = __ldg(&hs[sb.w * 4 + q]);
        acc_row(acc, r0); acc_row(acc, r1); acc_row(acc, r2); acc_row(acc, r3);
        acc_row(acc, r4); acc_row(acc, r5); acc_row(acc, r6); acc_row(acc, r7);
        e += 8;
    }
    if (e + 3 < end) {
        int4 s = __ldg(&row4[e >> 2]);
        uint2 r0 = __ldg(&hs[s.x * 4 + q]);
        uint2 r1 = __ldg(&hs[s.y * 4 + q]);
        uint2 r2 = __ldg(&hs[s.z * 4 + q]);
        uint2 r3 = __ldg(&hs[s.w * 4 + q]);
        acc_row(acc, r0); acc_row(acc, r1);
        acc_row(acc, r2); acc_row(acc, r3);
        e += 4;
    }
    for (; e < end; e++)
        acc_row(acc, __ldg(&hs[__ldg(&row[e]) * 4 + q]));
    return acc;
}

// Gather hs1 -> ReLU(bias) -> 16x16 W_mid matmul -> hs2 (half).
__global__ void __launch_bounds__(256, 4)
k_gatherA(const float* __restrict__ Wm,
          const float* __restrict__ bin, int n) {
    __shared__ float w[256];
    __shared__ float bsh[16];
    if (threadIdx.x < 256) w[threadIdx.x] = Wm[threadIdx.x];
    if (threadIdx.x < 16) bsh[threadIdx.x] = bin[threadIdx.x];
    __syncthreads();
    int t = blockIdx.x * blockDim.x + threadIdx.x;
    int i = t >> 2;
    int q = t & 3;
    if (i >= n) return;
    float4 acc = gather_rows((const uint2*)g_hs1, i, q);
    float di = g_dinv[i];
    float4 a;
    a.x = fmaxf(di * acc.x + bsh[4*q+0], 0.0f);
    a.y = fmaxf(di * acc.y + bsh[4*q+1], 0.0f);
    a.z = fmaxf(di * acc.z + bsh[4*q+2], 0.0f);
    a.w = fmaxf(di * acc.w + bsh[4*q+3], 0.0f);
    float4 o = make_float4(0.f, 0.f, 0.f, 0.f);
    int base = threadIdx.x & ~3;
#pragma unroll
    for (int sq = 0; sq < 4; sq++) {
        float ak0 = __shfl_sync(0xffffffffu, a.x, base + sq);
        float ak1 = __shfl_sync(0xffffffffu, a.y, base + sq);
        float ak2 = __shfl_sync(0xffffffffu, a.z, base + sq);
        float ak3 = __shfl_sync(0xffffffffu, a.w, base + sq);
        const float* w0 = &w[(4*sq + 0) * 16 + 4*q];
        const float* w1 = &w[(4*sq + 1) * 16 + 4*q];
        const float* w2 = &w[(4*sq + 2) * 16 + 4*q];
        const float* w3 = &w[(4*sq + 3) * 16 + 4*q];
        o.x += ak0*w0[0] + ak1*w1[0] + ak2*w2[0] + ak3*w3[0];
        o.y += ak0*w0[1] + ak1*w1[1] + ak2*w2[1] + ak3*w3[1];
        o.z += ak0*w0[2] + ak1*w1[2] + ak2*w2[2] + ak3*w3[2];
        o.w += ak0*w0[3] + ak1*w1[3] + ak2*w2[3] + ak3*w3[3];
    }
    uint2 pk;
    pk.x = h2u(__floats2half2_rn(o.x * di, o.y * di));
    pk.y = h2u(__floats2half2_rn(o.z * di, o.w * di));
    ((uint2*)g_hs2)[i * 4 + q] = pk;
}

// Gather hs2 -> ReLU(bias) -> dot W_out -> hs3 (fp32).
__global__ void __launch_bounds__(256, 4)
k_gatherB(const float* __restrict__ bmid,
          const float* __restrict__ Wout, int n) {
    __shared__ float w[16];
    __shared__ float bsh[16];
    if (threadIdx.x < 16) { w[threadIdx.x] = Wout[threadIdx.x]; bsh[threadIdx.x] = bmid[threadIdx.x]; }
    __syncthreads();
    int t = blockIdx.x * blockDim.x + threadIdx.x;
    int i = t >> 2;
    int q = t & 3;
    if (i >= n) return;
    float4 acc = gather_rows((const uint2*)g_hs2, i, q);
    float di = g_dinv[i];
    float s = fmaxf(di * acc.x + bsh[4*q+0], 0.0f) * w[4*q+0]
            + fmaxf(di * acc.y + bsh[4*q+1], 0.0f) * w[4*q+1]
            + fmaxf(di * acc.z + bsh[4*q+2], 0.0f) * w[4*q+2]
            + fmaxf(di * acc.w + bsh[4*q+3], 0.0f) * w[4*q+3];
    s += __shfl_xor_sync(0xffffffffu, s, 1);
    s += __shfl_xor_sync(0xffffffffu, s, 2);
    if (q == 0) g_hs3[i] = s * di;
}

// Gather hs3 -> sigmoid -> out. 1 thread/node, 16-edge unroll.
__global__ void __launch_bounds__(256, 4)
k_gatherC(const float* __restrict__ bout,
          float* __restrict__ out, int n) {
    int i = blockIdx.x * blockDim.x + threadIdx.x;
    if (i >= n) return;
    float acc = g_hs3[i];
    const int4* __restrict__ row4 = (const int4*)&g_bkt[i * CAP];
    const int*  __restrict__ row  = &g_bkt[i * CAP];
    int end = min(g_cnt[i], CAP);
    int e = 0;
    for (; e + 15 < end; e += 16) {
        int4 sa = __ldg(&row4[(e >> 2) + 0]);
        int4 sb = __ldg(&row4[(e >> 2) + 1]);
        int4 sc = __ldg(&row4[(e >> 2) + 2]);
        int4 sd = __ldg(&row4[(e >> 2) + 3]);
        float v0 = __ldg(&g_hs3[sa.x]);
        float v1 = __ldg(&g_hs3[sa.y]);
        float v2 = __ldg(&g_hs3[sa.z]);
        float v3 = __ldg(&g_hs3[sa.w]);
        float v4 = __ldg(&g_hs3[sb.x]);
        float v5 = __ldg(&g_hs3[sb.y]);
        float v6 = __ldg(&g_hs3[sb.z]);
        float v7 = __ldg(&g_hs3[sb.w]);
        float v8 = __ldg(&g_hs3[sc.x]);
        float v9 = __ldg(&g_hs3[sc.y]);
        float vA = __ldg(&g_hs3[sc.z]);
        float vB = __ldg(&g_hs3[sc.w]);
        float vC = __ldg(&g_hs3[sd.x]);
        float vD = __ldg(&g_hs3[sd.y]);
        float vE = __ldg(&g_hs3[sd.z]);
        float vF = __ldg(&g_hs3[sd.w]);
        acc += (((v0 + v1) + (v2 + v3)) + ((v4 + v5) + (v6 + v7)))
             + (((v8 + v9) + (vA + vB)) + ((vC + vD) + (vE + vF)));
    }
    if (e + 7 < end) {
        int4 sa = __ldg(&row4[(e >> 2) + 0]);
        int4 sb = __ldg(&row4[(e >> 2) + 1]);
        float v0 = __ldg(&g_hs3[sa.x]);
        float v1 = __ldg(&g_hs3[sa.y]);
        float v2 = __ldg(&g_hs3[sa.z]);
        float v3 = __ldg(&g_hs3[sa.w]);
        float v4 = __ldg(&g_hs3[sb.x]);
        float v5 = __ldg(&g_hs3[sb.y]);
        float v6 = __ldg(&g_hs3[sb.z]);
        float v7 = __ldg(&g_hs3[sb.w]);
        acc += ((v0 + v1) + (v2 + v3)) + ((v4 + v5) + (v6 + v7));
        e += 8;
    }
    if (e + 3 < end) {
        int4 s = __ldg(&row4[e >> 2]);
        float v0 = __ldg(&g_hs3[s.x]);
        float v1 = __ldg(&g_hs3[s.y]);
        float v2 = __ldg(&g_hs3[s.z]);
        float v3 = __ldg(&g_hs3[s.w]);
        acc += (v0 + v1) + (v2 + v3);
        e += 4;
    }
    for (; e < end; e++)
        acc += __ldg(&g_hs3[__ldg(&row[e])]);
    float v = g_dinv[i] * acc + bout[0];
    out[i] = 1.0f / (1.0f + __expf(-v));
}

// ---------------- launch ---------------------------------------------------------------

extern "C" void kernel_launch(void* const* d_in, const int* in_sizes, int n_in,
                              void* d_out, int out_size) {
    const float* x    = (const float*)d_in[0];
    const void*  ei   = d_in[1];
    const float* Win  = (const float*)d_in[2];
    const float* bin  = (const float*)d_in[3];
    const float* Wmid = (const float*)d_in[4];
    const float* bmid = (const float*)d_in[5];
    const float* Wout = (const float*)d_in[6];
    const float* bout = (const float*)d_in[7];
    float* out = (float*)d_out;

    int n  = in_sizes[0] / 3;   // 150000
    int ne = in_sizes[1] / 2;   // 4800000
    if (n > NN) n = NN;
    if (ne > EE) ne = EE;

    const int B = 256;
    int gn  = (n + B - 1) / B;
    int ge2 = ((ne + 1) / 2 + B - 1) / B;
    int gq  = (n * 4 + B - 1) / B;

    k_init<<<gn, B>>>(ei, ne, n);
    k_build<<<ge2, B>>>(ei, ne);
    k_node1<<<gn, B>>>(x, Win, n);
    k_gatherA<<<gq, B>>>(Wmid, bin, n);
    k_gatherB<<<gq, B>>>(bmid, Wout, n);
    k_gatherC<<<gn, B>>>(bout, out, n);
    (void)n_in; (void)out_size;
}

// round 15
// speedup vs baseline: 1.0081x; 1.0081x over previous
#include <cuda_runtime.h>
#include <cuda_fp16.h>
#include <math.h>

#define NN 150000
#define EE 4800000
#define H 16
#define CAP 128              // bucket capacity per node (max degree ~75 for Poisson(32))

// ---------------- scratch (device globals) ----------------------------------
__device__ int   g_is64;
__device__ int   g_cnt[NN];                         // in-degree (excl. self loop)
__device__ __align__(16) int g_bkt[NN * CAP];       // per-dst src buckets (76.8 MB)
__device__ float g_dinv[NN];
__device__ __align__(128) __half2 g_hs1[NN * 8];    // 16 halves per node (32B rows)
__device__ __align__(128) __half2 g_hs2[NN * 8];
__device__ float g_hs3[NN];

__device__ __forceinline__ unsigned h2u(__half2 h) {
    return *reinterpret_cast<unsigned*>(&h);
}

// ---------------- init: zero counts + detect dtype ------------------------------

__global__ void k_init(const void* __restrict__ ei, int ne, int n) {
    int i = blockIdx.x * blockDim.x + threadIdx.x;
    if (i < n) g_cnt[i] = 0;
    if (blockIdx.x == 0 && threadIdx.x < 32) {
        const long long* p = (const long long*)ei;
        int lane = threadIdx.x;
        int bad = 0;
        int lim = ne < 1024 ? ne : 1024;
        for (int e = lane; e < lim; e += 32) {
            long long v = p[e];
            if (v < 0 || v >= NN) bad = 1;
        }
        unsigned m = __ballot_sync(0xffffffffu, bad);
        if (lane == 0) g_is64 = (m == 0) ? 1 : 0;
    }
}

// ---------------- single-pass bucket build (2 edges/thread) -----------------------

__global__ void k_build(const void* __restrict__ ei, int ne) {
    int t = blockIdx.x * blockDim.x + threadIdx.x;
    int e0 = t * 2;
    if (e0 >= ne) return;
    bool two = (e0 + 1 < ne);
    int s0, d0, s1 = 0, d1 = 0;
    if (g_is64) {
        const long long* p = (const long long*)ei;
        if (two) {
            longlong2 sp = *(const longlong2*)&p[e0];
            longlong2 dp = *(const longlong2*)&p[ne + e0];
            s0 = (int)sp.x; s1 = (int)sp.y;
            d0 = (int)dp.x; d1 = (int)dp.y;
        } else {
            s0 = (int)p[e0];
            d0 = (int)p[ne + e0];
        }
    } else {
        const int* p = (const int*)ei;
        if (two) {
            int2 sp = *(const int2*)&p[e0];
            int2 dp = *(const int2*)&p[ne + e0];
            s0 = sp.x; s1 = sp.y; d0 = dp.x; d1 = dp.y;
        } else {
            s0 = p[e0];
            d0 = p[ne + e0];
        }
    }
    s0 = min(max(s0, 0), NN - 1); d0 = min(max(d0, 0), NN - 1);
    int p0 = atomicAdd(&g_cnt[d0], 1);
    if (p0 < CAP) g_bkt[d0 * CAP + p0] = s0;
    if (two) {
        s1 = min(max(s1, 0), NN - 1); d1 = min(max(d1, 0), NN - 1);
        int p1 = atomicAdd(&g_cnt[d1], 1);
        if (p1 < CAP) g_bkt[d1 * CAP + p1] = s1;
    }
}

// ---------------- layer-1 node transform ------------------------------------------

__global__ void k_node1(const float* __restrict__ x,
                        const float* __restrict__ Win, int n) {
    __shared__ float w[48];
    if (threadIdx.x < 48) w[threadIdx.x] = Win[threadIdx.x];
    __syncthreads();
    int i = blockIdx.x * blockDim.x + threadIdx.x;
    if (i >= n) return;
    float di = rsqrtf((float)(g_cnt[i] + 1));
    g_dinv[i] = di;
    float x0 = x[i * 3 + 0], x1 = x[i * 3 + 1], x2 = x[i * 3 + 2];
    float v[16];
#pragma unroll
    for (int j = 0; j < 16; j++)
        v[j] = di * (x0 * w[j] + x1 * w[16 + j] + x2 * w[32 + j]);
    uint4 pk0, pk1;
    pk0.x = h2u(__floats2half2_rn(v[0],  v[1]));
    pk0.y = h2u(__floats2half2_rn(v[2],  v[3]));
    pk0.z = h2u(__floats2half2_rn(v[4],  v[5]));
    pk0.w = h2u(__floats2half2_rn(v[6],  v[7]));
    pk1.x = h2u(__floats2half2_rn(v[8],  v[9]));
    pk1.y = h2u(__floats2half2_rn(v[10], v[11]));
    pk1.z = h2u(__floats2half2_rn(v[12], v[13]));
    pk1.w = h2u(__floats2half2_rn(v[14], v[15]));
    ((uint4*)g_hs1)[i * 2 + 0] = pk0;
    ((uint4*)g_hs1)[i * 2 + 1] = pk1;
}

// ---------------- fused gather kernels (half2 rows, quad-per-node) ------------------

__device__ __forceinline__ void acc_row(float4& acc, uint2 raw) {
    float2 f0 = __half22float2(*reinterpret_cast<const __half2*>(&raw.x));
    float2 f1 = __half22float2(*reinterpret_cast<const __half2*>(&raw.y));
    acc.x += f0.x; acc.y += f0.y; acc.z += f1.x; acc.w += f1.y;
}

// Bucket gather: 8-edge unroll, dual accumulators, then 4/1 tails.
__device__ __forceinline__ float4 gather_rows(const uint2* __restrict__ hs,
                                              int i, int q) {
    float4 acc0 = make_float4(0.f, 0.f, 0.f, 0.f);
    float4 acc1 = make_float4(0.f, 0.f, 0.f, 0.f);
    acc_row(acc0, __ldg(&hs[i * 4 + q]));          // self loop
    const int4* __restrict__ row4 = (const int4*)&g_bkt[i * CAP];
    const int*  __restrict__ row  = &g_bkt[i * CAP];
    int end = min(g_cnt[i], CAP);
    int e = 0;
    for (; e + 7 < end; e += 8) {
        int4 sa = __ldg(&row4[(e >> 2) + 0]);
        int4 sb = __ldg(&row4[(e >> 2) + 1]);
        uint2 r0 = __ldg(&hs[sa.x * 4 + q]);
        uint2 r1 = __ldg(&hs[sa.y * 4 + q]);
        uint2 r2 = __ldg(&hs[sa.z * 4 + q]);
        uint2 r3 = __ldg(&hs[sa.w * 4 + q]);
        uint2 r4 = __ldg(&hs[sb.x * 4 + q]);
        uint2 r5 = __ldg(&hs[sb.y * 4 + q]);
        uint2 r6 = __ldg(&hs[sb.z * 4 + q]);
        uint2 r7 = __ldg(&hs[sb.w * 4 + q]);
        acc_row(acc0, r0); acc_row(acc1, r1);
        acc_row(acc0, r2); acc_row(acc1, r3);
        acc_row(acc0, r4); acc_row(acc1, r5);
        acc_row(acc0, r6); acc_row(acc1, r7);
    }
    if (e + 3 < end) {
        int4 s = __ldg(&row4[e >> 2]);
        uint2 r0 = __ldg(&hs[s.x * 4 + q]);
        uint2 r1 = __ldg(&hs[s.y * 4 + q]);
        uint2 r2 = __ldg(&hs[s.z * 4 + q]);
        uint2 r3 = __ldg(&hs[s.w * 4 + q]);
        acc_row(acc0, r0); acc_row(acc1, r1);
        acc_row(acc0, r2); acc_row(acc1, r3);
        e += 4;
    }
    for (; e < end; e++)
        acc_row(acc0, __ldg(&hs[__ldg(&row[e]) * 4 + q]));
    acc0.x += acc1.x; acc0.y += acc1.y;
    acc0.z += acc1.z; acc0.w += acc1.w;
    return acc0;
}

// Gather hs1 -> ReLU(bias) -> 16x16 W_mid matmul -> hs2 (half).
__global__ void k_gatherA(const float* __restrict__ Wm,
                          const float* __restrict__ bin, int n) {
    __shared__ float w[256];
    __shared__ float bsh[16];
    if (threadIdx.x < 256) w[threadIdx.x] = Wm[threadIdx.x];
    if (threadIdx.x < 16) bsh[threadIdx.x] = bin[threadIdx.x];
    __syncthreads();
    int t = blockIdx.x * blockDim.x + threadIdx.x;
    int i = t >> 2;
    int q = t & 3;
    if (i >= n) return;
    float4 acc = gather_rows((const uint2*)g_hs1, i, q);
    float di = g_dinv[i];
    float4 a;
    a.x = fmaxf(di * acc.x + bsh[4*q+0], 0.0f);
    a.y = fmaxf(di * acc.y + bsh[4*q+1], 0.0f);
    a.z = fmaxf(di * acc.z + bsh[4*q+2], 0.0f);
    a.w = fmaxf(di * acc.w + bsh[4*q+3], 0.0f);
    float4 o = make_float4(0.f, 0.f, 0.f, 0.f);
    int base = threadIdx.x & ~3;
#pragma unroll
    for (int sq = 0; sq < 4; sq++) {
        float ak0 = __shfl_sync(0xffffffffu, a.x, base + sq);
        float ak1 = __shfl_sync(0xffffffffu, a.y, base + sq);
        float ak2 = __shfl_sync(0xffffffffu, a.z, base + sq);
        float ak3 = __shfl_sync(0xffffffffu, a.w, base + sq);
        const float* w0 = &w[(4*sq + 0) * 16 + 4*q];
        const float* w1 = &w[(4*sq + 1) * 16 + 4*q];
        const float* w2 = &w[(4*sq + 2) * 16 + 4*q];
        const float* w3 = &w[(4*sq + 3) * 16 + 4*q];
        o.x += ak0*w0[0] + ak1*w1[0] + ak2*w2[0] + ak3*w3[0];
        o.y += ak0*w0[1] + ak1*w1[1] + ak2*w2[1] + ak3*w3[1];
        o.z += ak0*w0[2] + ak1*w1[2] + ak2*w2[2] + ak3*w3[2];
        o.w += ak0*w0[3] + ak1*w1[3] + ak2*w2[3] + ak3*w3[3];
    }
    uint2 pk;
    pk.x = h2u(__floats2half2_rn(o.x * di, o.y * di));
    pk.y = h2u(__floats2half2_rn(o.z * di, o.w * di));
    ((uint2*)g_hs2)[i * 4 + q] = pk;
}

// Gather hs2 -> ReLU(bias) -> dot W_out -> hs3 (fp32).
__global__ void k_gatherB(const float* __restrict__ bmid,
                          const float* __restrict__ Wout, int n) {
    __shared__ float w[16];
    __shared__ float bsh[16];
    if (threadIdx.x < 16) { w[threadIdx.x] = Wout[threadIdx.x]; bsh[threadIdx.x] = bmid[threadIdx.x]; }
    __syncthreads();
    int t = blockIdx.x * blockDim.x + threadIdx.x;
    int i = t >> 2;
    int q = t & 3;
    if (i >= n) return;
    float4 acc = gather_rows((const uint2*)g_hs2, i, q);
    float di = g_dinv[i];
    float s = fmaxf(di * acc.x + bsh[4*q+0], 0.0f) * w[4*q+0]
            + fmaxf(di * acc.y + bsh[4*q+1], 0.0f) * w[4*q+1]
            + fmaxf(di * acc.z + bsh[4*q+2], 0.0f) * w[4*q+2]
            + fmaxf(di * acc.w + bsh[4*q+3], 0.0f) * w[4*q+3];
    s += __shfl_xor_sync(0xffffffffu, s, 1);
    s += __shfl_xor_sync(0xffffffffu, s, 2);
    if (q == 0) g_hs3[i] = s * di;
}

// Gather hs3 -> sigmoid -> out. 1 thread/node, 8-edge unroll, dual accumulators.
__global__ void k_gatherC(const float* __restrict__ bout,
                          float* __restrict__ out, int n) {
    int i = blockIdx.x * blockDim.x + threadIdx.x;
    if (i >= n) return;
    float acc0 = g_hs3[i];
    float acc1 = 0.0f;
    const int4* __restrict__ row4 = (const int4*)&g_bkt[i * CAP];
    const int*  __restrict__ row  = &g_bkt[i * CAP];
    int end = min(g_cnt[i], CAP);
    int e = 0;
    for (; e + 7 < end; e += 8) {
        int4 sa = __ldg(&row4[(e >> 2) + 0]);
        int4 sb = __ldg(&row4[(e >> 2) + 1]);
        float v0 = __ldg(&g_hs3[sa.x]);
        float v1 = __ldg(&g_hs3[sa.y]);
        float v2 = __ldg(&g_hs3[sa.z]);
        float v3 = __ldg(&g_hs3[sa.w]);
        float v4 = __ldg(&g_hs3[sb.x]);
        float v5 = __ldg(&g_hs3[sb.y]);
        float v6 = __ldg(&g_hs3[sb.z]);
        float v7 = __ldg(&g_hs3[sb.w]);
        acc0 += (v0 + v1) + (v2 + v3);
        acc1 += (v4 + v5) + (v6 + v7);
    }
    if (e + 3 < end) {
        int4 s = __ldg(&row4[e >> 2]);
        float v0 = __ldg(&g_hs3[s.x]);
        float v1 = __ldg(&g_hs3[s.y]);
        float v2 = __ldg(&g_hs3[s.z]);
        float v3 = __ldg(&g_hs3[s.w]);
        acc0 += (v0 + v1) + (v2 + v3);
        e += 4;
    }
    for (; e < end; e++)
        acc0 += __ldg(&g_hs3[__ldg(&row[e])]);
    float v = g_dinv[i] * (acc0 + acc1) + bout[0];
    out[i] = 1.0f / (1.0f + __expf(-v));
}

// ---------------- launch ---------------------------------------------------------------

extern "C" void kernel_launch(void* const* d_in, const int* in_sizes, int n_in,
                              void* d_out, int out_size) {
    const float* x    = (const float*)d_in[0];
    const void*  ei   = d_in[1];
    const float* Win  = (const float*)d_in[2];
    const float* bin  = (const float*)d_in[3];
    const float* Wmid = (const float*)d_in[4];
    const float* bmid = (const float*)d_in[5];
    const float* Wout = (const float*)d_in[6];
    const float* bout = (const float*)d_in[7];
    float* out = (float*)d_out;

    int n  = in_sizes[0] / 3;   // 150000
    int ne = in_sizes[1] / 2;   // 4800000
    if (n > NN) n = NN;
    if (ne > EE) ne = EE;

    const int B = 256;
    int gn  = (n + B - 1) / B;
    int ge2 = ((ne + 1) / 2 + B - 1) / B;
    int gq  = (n * 4 + B - 1) / B;

    k_init<<<gn, B>>>(ei, ne, n);
    k_build<<<ge2, B>>>(ei, ne);
    k_node1<<<gn, B>>>(x, Win, n);
    k_gatherA<<<gq, B>>>(Wmid, bin, n);
    k_gatherB<<<gq, B>>>(bmid, Wout, n);
    k_gatherC<<<gn, B>>>(bout, out, n);
    (void)n_in; (void)out_size;
}

// round 16
// speedup vs baseline: 1.0263x; 1.0181x over previous
#include <cuda_runtime.h>
#include <cuda_fp16.h>
#include <math.h>

#define NN 150000
#define EE 4800000
#define H 16
#define CAP 128              // bucket capacity per node (max degree ~75 for Poisson(32))

// ---------------- scratch (device globals) ----------------------------------
__device__ int   g_is64;
__device__ int   g_cnt[NN];                         // in-degree (excl. self loop)
__device__ __align__(16) int g_bkt[NN * CAP];       // per-dst src buckets (76.8 MB)
__device__ float g_dinv[NN];
__device__ __align__(128) __half2 g_hs1[NN * 8];    // 16 halves per node (32B rows)
__device__ __align__(128) __half2 g_hs2[NN * 8];
__device__ float g_hs3[NN];

__device__ __forceinline__ unsigned h2u(__half2 h) {
    return *reinterpret_cast<unsigned*>(&h);
}

// ---------------- init: zero counts + detect dtype ------------------------------

__global__ void k_init(const void* __restrict__ ei, int ne, int n) {
    int i = blockIdx.x * blockDim.x + threadIdx.x;
    if (i < n) g_cnt[i] = 0;
    if (blockIdx.x == 0 && threadIdx.x < 32) {
        const long long* p = (const long long*)ei;
        int lane = threadIdx.x;
        int bad = 0;
        int lim = ne < 1024 ? ne : 1024;
        for (int e = lane; e < lim; e += 32) {
            long long v = p[e];
            if (v < 0 || v >= NN) bad = 1;
        }
        unsigned m = __ballot_sync(0xffffffffu, bad);
        if (lane == 0) g_is64 = (m == 0) ? 1 : 0;
    }
}

// ---------------- single-pass bucket build (2 edges/thread) -----------------------

__global__ void k_build(const void* __restrict__ ei, int ne) {
    int t = blockIdx.x * blockDim.x + threadIdx.x;
    int e0 = t * 2;
    if (e0 >= ne) return;
    bool two = (e0 + 1 < ne);
    int s0, d0, s1 = 0, d1 = 0;
    if (g_is64) {
        const long long* p = (const long long*)ei;
        if (two) {
            longlong2 sp = *(const longlong2*)&p[e0];
            longlong2 dp = *(const longlong2*)&p[ne + e0];
            s0 = (int)sp.x; s1 = (int)sp.y;
            d0 = (int)dp.x; d1 = (int)dp.y;
        } else {
            s0 = (int)p[e0];
            d0 = (int)p[ne + e0];
        }
    } else {
        const int* p = (const int*)ei;
        if (two) {
            int2 sp = *(const int2*)&p[e0];
            int2 dp = *(const int2*)&p[ne + e0];
            s0 = sp.x; s1 = sp.y; d0 = dp.x; d1 = dp.y;
        } else {
            s0 = p[e0];
            d0 = p[ne + e0];
        }
    }
    s0 = min(max(s0, 0), NN - 1); d0 = min(max(d0, 0), NN - 1);
    int p0 = atomicAdd(&g_cnt[d0], 1);
    if (p0 < CAP) g_bkt[d0 * CAP + p0] = s0;
    if (two) {
        s1 = min(max(s1, 0), NN - 1); d1 = min(max(d1, 0), NN - 1);
        int p1 = atomicAdd(&g_cnt[d1], 1);
        if (p1 < CAP) g_bkt[d1 * CAP + p1] = s1;
    }
}

// ---------------- layer-1 node transform ------------------------------------------

__global__ void k_node1(const float* __restrict__ x,
                        const float* __restrict__ Win, int n) {
    __shared__ float w[48];
    if (threadIdx.x < 48) w[threadIdx.x] = Win[threadIdx.x];
    __syncthreads();
    int i = blockIdx.x * blockDim.x + threadIdx.x;
    if (i >= n) return;
    float di = rsqrtf((float)(g_cnt[i] + 1));
    g_dinv[i] = di;
    float x0 = x[i * 3 + 0], x1 = x[i * 3 + 1], x2 = x[i * 3 + 2];
    float v[16];
#pragma unroll
    for (int j = 0; j < 16; j++)
        v[j] = di * (x0 * w[j] + x1 * w[16 + j] + x2 * w[32 + j]);
    uint4 pk0, pk1;
    pk0.x = h2u(__floats2half2_rn(v[0],  v[1]));
    pk0.y = h2u(__floats2half2_rn(v[2],  v[3]));
    pk0.z = h2u(__floats2half2_rn(v[4],  v[5]));
    pk0.w = h2u(__floats2half2_rn(v[6],  v[7]));
    pk1.x = h2u(__floats2half2_rn(v[8],  v[9]));
    pk1.y = h2u(__floats2half2_rn(v[10], v[11]));
    pk1.z = h2u(__floats2half2_rn(v[12], v[13]));
    pk1.w = h2u(__floats2half2_rn(v[14], v[15]));
    ((uint4*)g_hs1)[i * 2 + 0] = pk0;
    ((uint4*)g_hs1)[i * 2 + 1] = pk1;
}

// ---------------- fused gather kernels (half2 rows, quad-per-node) ------------------

__device__ __forceinline__ void acc_row(float4& acc, uint2 raw) {
    float2 f0 = __half22float2(*reinterpret_cast<const __half2*>(&raw.x));
    float2 f1 = __half22float2(*reinterpret_cast<const __half2*>(&raw.y));
    acc.x += f0.x; acc.y += f0.y; acc.z += f1.x; acc.w += f1.y;
}

// Bucket gather: 8-edge unroll (2 int4 idx loads, 8 independent row loads), then 4/1 tails.
__device__ __forceinline__ float4 gather_rows(const uint2* __restrict__ hs,
                                              int i, int q) {
    float4 acc = make_float4(0.f, 0.f, 0.f, 0.f);
    acc_row(acc, __ldg(&hs[i * 4 + q]));           // self loop
    const int4* __restrict__ row4 = (const int4*)&g_bkt[i * CAP];
    const int*  __restrict__ row  = &g_bkt[i * CAP];
    int end = min(g_cnt[i], CAP);
    int e = 0;
    for (; e + 7 < end; e += 8) {
        int4 sa = __ldg(&row4[(e >> 2) + 0]);
        int4 sb = __ldg(&row4[(e >> 2) + 1]);
        uint2 r0 = __ldg(&hs[sa.x * 4 + q]);
        uint2 r1 = __ldg(&hs[sa.y * 4 + q]);
        uint2 r2 = __ldg(&hs[sa.z * 4 + q]);
        uint2 r3 = __ldg(&hs[sa.w * 4 + q]);
        uint2 r4 = __ldg(&hs[sb.x * 4 + q]);
        uint2 r5 = __ldg(&hs[sb.y * 4 + q]);
        uint2 r6 = __ldg(&hs[sb.z * 4 + q]);
        uint2 r7 = __ldg(&hs[sb.w * 4 + q]);
        acc_row(acc, r0); acc_row(acc, r1);
        acc_row(acc, r2); acc_row(acc, r3);
        acc_row(acc, r4); acc_row(acc, r5);
        acc_row(acc, r6); acc_row(acc, r7);
    }
    if (e + 3 < end) {
        int4 s = __ldg(&row4[e >> 2]);
        uint2 r0 = __ldg(&hs[s.x * 4 + q]);
        uint2 r1 = __ldg(&hs[s.y * 4 + q]);
        uint2 r2 = __ldg(&hs[s.z * 4 + q]);
        uint2 r3 = __ldg(&hs[s.w * 4 + q]);
        acc_row(acc, r0); acc_row(acc, r1);
        acc_row(acc, r2); acc_row(acc, r3);
        e += 4;
    }
    for (; e < end; e++)
        acc_row(acc, __ldg(&hs[__ldg(&row[e]) * 4 + q]));
    return acc;
}

// Gather hs1 -> ReLU(bias) -> 16x16 W_mid matmul -> hs2 (half).
__global__ void k_gatherA(const float* __restrict__ Wm,
                          const float* __restrict__ bin, int n) {
    __shared__ float w[256];
    __shared__ float bsh[16];
    if (threadIdx.x < 256) w[threadIdx.x] = Wm[threadIdx.x];
    if (threadIdx.x < 16) bsh[threadIdx.x] = bin[threadIdx.x];
    __syncthreads();
    int t = blockIdx.x * blockDim.x + threadIdx.x;
    int i = t >> 2;
    int q = t & 3;
    if (i >= n) return;
    float4 acc = gather_rows((const uint2*)g_hs1, i, q);
    float di = g_dinv[i];
    float4 a;
    a.x = fmaxf(di * acc.x + bsh[4*q+0], 0.0f);
    a.y = fmaxf(di * acc.y + bsh[4*q+1], 0.0f);
    a.z = fmaxf(di * acc.z + bsh[4*q+2], 0.0f);
    a.w = fmaxf(di * acc.w + bsh[4*q+3], 0.0f);
    float4 o = make_float4(0.f, 0.f, 0.f, 0.f);
    int base = threadIdx.x & ~3;
#pragma unroll
    for (int sq = 0; sq < 4; sq++) {
        float ak0 = __shfl_sync(0xffffffffu, a.x, base + sq);
        float ak1 = __shfl_sync(0xffffffffu, a.y, base + sq);
        float ak2 = __shfl_sync(0xffffffffu, a.z, base + sq);
        float ak3 = __shfl_sync(0xffffffffu, a.w, base + sq);
        const float* w0 = &w[(4*sq + 0) * 16 + 4*q];
        const float* w1 = &w[(4*sq + 1) * 16 + 4*q];
        const float* w2 = &w[(4*sq + 2) * 16 + 4*q];
        const float* w3 = &w[(4*sq + 3) * 16 + 4*q];
        o.x += ak0*w0[0] + ak1*w1[0] + ak2*w2[0] + ak3*w3[0];
        o.y += ak0*w0[1] + ak1*w1[1] + ak2*w2[1] + ak3*w3[1];
        o.z += ak0*w0[2] + ak1*w1[2] + ak2*w2[2] + ak3*w3[2];
        o.w += ak0*w0[3] + ak1*w1[3] + ak2*w2[3] + ak3*w3[3];
    }
    uint2 pk;
    pk.x = h2u(__floats2half2_rn(o.x * di, o.y * di));
    pk.y = h2u(__floats2half2_rn(o.z * di, o.w * di));
    ((uint2*)g_hs2)[i * 4 + q] = pk;
}

// Gather hs2 -> ReLU(bias) -> dot W_out -> hs3 (fp32).
__global__ void k_gatherB(const float* __restrict__ bmid,
                          const float* __restrict__ Wout, int n) {
    __shared__ float w[16];
    __shared__ float bsh[16];
    if (threadIdx.x < 16) { w[threadIdx.x] = Wout[threadIdx.x]; bsh[threadIdx.x] = bmid[threadIdx.x]; }
    __syncthreads();
    int t = blockIdx.x * blockDim.x + threadIdx.x;
    int i = t >> 2;
    int q = t & 3;
    if (i >= n) return;
    float4 acc = gather_rows((const uint2*)g_hs2, i, q);
    float di = g_dinv[i];
    float s = fmaxf(di * acc.x + bsh[4*q+0], 0.0f) * w[4*q+0]
            + fmaxf(di * acc.y + bsh[4*q+1], 0.0f) * w[4*q+1]
            + fmaxf(di * acc.z + bsh[4*q+2], 0.0f) * w[4*q+2]
            + fmaxf(di * acc.w + bsh[4*q+3], 0.0f) * w[4*q+3];
    s += __shfl_xor_sync(0xffffffffu, s, 1);
    s += __shfl_xor_sync(0xffffffffu, s, 2);
    if (q == 0) g_hs3[i] = s * di;
}

// Gather hs3 -> sigmoid -> out. 1 thread/node, 8-edge unroll.
__global__ void k_gatherC(const float* __restrict__ bout,
                          float* __restrict__ out, int n) {
    int i = blockIdx.x * blockDim.x + threadIdx.x;
    if (i >= n) return;
    float acc = g_hs3[i];
    const int4* __restrict__ row4 = (const int4*)&g_bkt[i * CAP];
    const int*  __restrict__ row  = &g_bkt[i * CAP];
    int end = min(g_cnt[i], CAP);
    int e = 0;
    for (; e + 7 < end; e += 8) {
        int4 sa = __ldg(&row4[(e >> 2) + 0]);
        int4 sb = __ldg(&row4[(e >> 2) + 1]);
        float v0 = __ldg(&g_hs3[sa.x]);
        float v1 = __ldg(&g_hs3[sa.y]);
        float v2 = __ldg(&g_hs3[sa.z]);
        float v3 = __ldg(&g_hs3[sa.w]);
        float v4 = __ldg(&g_hs3[sb.x]);
        float v5 = __ldg(&g_hs3[sb.y]);
        float v6 = __ldg(&g_hs3[sb.z]);
        float v7 = __ldg(&g_hs3[sb.w]);
        acc += ((v0 + v1) + (v2 + v3)) + ((v4 + v5) + (v6 + v7));
    }
    if (e + 3 < end) {
        int4 s = __ldg(&row4[e >> 2]);
        float v0 = __ldg(&g_hs3[s.x]);
        float v1 = __ldg(&g_hs3[s.y]);
        float v2 = __ldg(&g_hs3[s.z]);
        float v3 = __ldg(&g_hs3[s.w]);
        acc += (v0 + v1) + (v2 + v3);
        e += 4;
    }
    for (; e < end; e++)
        acc += __ldg(&g_hs3[__ldg(&row[e])]);
    float v = g_dinv[i] * acc + bout[0];
    out[i] = 1.0f / (1.0f + __expf(-v));
}

// ---------------- launch ---------------------------------------------------------------

extern "C" void kernel_launch(void* const* d_in, const int* in_sizes, int n_in,
                              void* d_out, int out_size) {
    const float* x    = (const float*)d_in[0];
    const void*  ei   = d_in[1];
    const float* Win  = (const float*)d_in[2];
    const float* bin  = (const float*)d_in[3];
    const float* Wmid = (const float*)d_in[4];
    const float* bmid = (const float*)d_in[5];
    const float* Wout = (const float*)d_in[6];
    const float* bout = (const float*)d_in[7];
    float* out = (float*)d_out;

    int n  = in_sizes[0] / 3;   // 150000
    int ne = in_sizes[1] / 2;   // 4800000
    if (n > NN) n = NN;
    if (ne > EE) ne = EE;

    const int B = 256;
    int gn  = (n + B - 1) / B;
    int ge2 = ((ne + 1) / 2 + B - 1) / B;
    int gq  = (n * 4 + B - 1) / B;

    k_init<<<gn, B>>>(ei, ne, n);
    k_build<<<ge2, B>>>(ei, ne);
    k_node1<<<gn, B>>>(x, Win, n);
    k_gatherA<<<gq, B>>>(Wmid, bin, n);
    k_gatherB<<<gq, B>>>(bmid, Wout, n);
    k_gatherC<<<gn, B>>>(bout, out, n);
    (void)n_in; (void)out_size;
}